// round 10
// baseline (speedup 1.0000x reference)
#include <cuda_runtime.h>
#include <cuda_fp16.h>
#include <cstdint>

// ============================================================================
// ContrastiveLoss: N=16384, D=256, T=0.07
// loss = mean_i [ log(sum_j exp((c_ij - 1)/T)) + (1 - selfdot_i)/T ]
// R9: INT8 IMMA m16n8k32 (half the tensor instructions vs HMMA.16816),
//     per-row scale quantization, exact s32 accumulation, fp32 de-scale in
//     the interleaved exp epilogue; diagonal substituted from fp32 selfdot.
// ============================================================================

#define N_ROWS 16384
#define DIM    256
#define TILE   128
#define NT     (N_ROWS / TILE)   // 128
#define THREADS 256
#define GRID   148
#define TOTAL_TILES (NT * (NT + 1) / 2)   // 8256

#define INV_T      14.285714285714286f
#define EX2_SCALE  20.60992915555662f   // log2(e)/0.07

__device__ int8_t g_emb8[N_ROWS * DIM];   // quantized rows (256B/row)
__device__ float g_scale[N_ROWS];         // per-row dequant scale s_i
__device__ float g_selfdot[N_ROWS];       // s_i^2 * sum(q^2)  (exact fp32)
__device__ float g_rowsum[N_ROWS];

// ---------------------------------------------------------------------------
__device__ __forceinline__ uint32_t smem_u32(const void* p) {
    uint32_t a;
    asm("{ .reg .u64 t; cvta.to.shared.u64 t, %1; cvt.u32.u64 %0, t; }" : "=r"(a) : "l"(p));
    return a;
}

__device__ __forceinline__ float ex2f(float x) {
    float y;
    asm("ex2.approx.ftz.f32 %0, %1;" : "=f"(y) : "f"(x));
    return y;
}

__device__ __forceinline__ void lm4(uint32_t addr, uint32_t r[4]) {
    asm volatile("ldmatrix.sync.aligned.m8n8.x4.shared.b16 {%0,%1,%2,%3}, [%4];"
                 : "=r"(r[0]), "=r"(r[1]), "=r"(r[2]), "=r"(r[3]) : "r"(addr));
}

// s8 x s8 -> s32, m16n8k32
__device__ __forceinline__ void imma16832(int c[4], const uint32_t a[4],
                                          uint32_t b0, uint32_t b1) {
    asm volatile(
        "mma.sync.aligned.m16n8k32.row.col.s32.s8.s8.s32 "
        "{%0,%1,%2,%3}, {%4,%5,%6,%7}, {%8,%9}, {%0,%1,%2,%3};"
        : "+r"(c[0]), "+r"(c[1]), "+r"(c[2]), "+r"(c[3])
        : "r"(a[0]), "r"(a[1]), "r"(a[2]), "r"(a[3]), "r"(b0), "r"(b1));
}

__device__ __forceinline__ void cp_async16(uint32_t dst, uint64_t src) {
    asm volatile("cp.async.cg.shared.global [%0], [%1], 16;" :: "r"(dst), "l"(src) : "memory");
}
__device__ __forceinline__ void cp_commit() {
    asm volatile("cp.async.commit_group;" ::: "memory");
}

// ---------------------------------------------------------------------------
// Kernel 1: normalize rows -> int8 (per-row scale), selfdot, zero g_rowsum
// ---------------------------------------------------------------------------
__global__ void __launch_bounds__(256) normalize_kernel(const float* __restrict__ in) {
    int row  = blockIdx.x * 8 + (threadIdx.x >> 5);
    int lane = threadIdx.x & 31;

    const float4* p = reinterpret_cast<const float4*>(in + (size_t)row * DIM);
    float4 a = p[lane];
    float4 b = p[lane + 32];

    float s = a.x*a.x + a.y*a.y + a.z*a.z + a.w*a.w
            + b.x*b.x + b.y*b.y + b.z*b.z + b.w*b.w;
    #pragma unroll
    for (int o = 16; o; o >>= 1) s += __shfl_xor_sync(0xffffffffu, s, o);
    float inv = 1.0f / sqrtf(s);

    float v[8] = {a.x*inv, a.y*inv, a.z*inv, a.w*inv,
                  b.x*inv, b.y*inv, b.z*inv, b.w*inv};

    float mx = 0.f;
    #pragma unroll
    for (int k = 0; k < 8; ++k) mx = fmaxf(mx, fabsf(v[k]));
    #pragma unroll
    for (int o = 16; o; o >>= 1) mx = fmaxf(mx, __shfl_xor_sync(0xffffffffu, mx, o));

    float sc  = mx * (1.0f / 127.0f);
    float isc = 127.0f / mx;

    int q[8];
    float sq = 0.f;
    #pragma unroll
    for (int k = 0; k < 8; ++k) {
        q[k] = __float2int_rn(v[k] * isc);
        float qf = (float)q[k];
        sq += qf * qf;
    }
    #pragma unroll
    for (int o = 16; o; o >>= 1) sq += __shfl_xor_sync(0xffffffffu, sq, o);

    // pack 8 int8 -> 2 int32
    uint32_t p0 = (uint32_t)(q[0] & 255) | ((uint32_t)(q[1] & 255) << 8)
                | ((uint32_t)(q[2] & 255) << 16) | ((uint32_t)(q[3] & 255) << 24);
    uint32_t p1 = (uint32_t)(q[4] & 255) | ((uint32_t)(q[5] & 255) << 8)
                | ((uint32_t)(q[6] & 255) << 16) | ((uint32_t)(q[7] & 255) << 24);

    uint32_t* out = reinterpret_cast<uint32_t*>(g_emb8 + (size_t)row * DIM);
    out[lane]      = p0;
    out[lane + 32] = p1;

    if (lane == 0) g_selfdot[row] = sc * sc * sq;
    if (lane == 1) g_scale[row]   = sc;
    if (lane == 2) g_rowsum[row]  = 0.f;
}

// ---------------------------------------------------------------------------
// Kernel 2: upper-triangle fused int8 GEMM + exp + row/col sums (persistent)
// smem: A 32KB + B double buffer 64KB
// ---------------------------------------------------------------------------
#define SM_A     0
#define SM_B0    32768
#define SM_B1    65536
#define SM_TOTAL 98304

extern __shared__ char dyn_smem[];

// stage one 128x256B int8 tile; rows 256B = 16x16B units, swizzled
__device__ __forceinline__ void stage_tile(uint32_t sdst, uint64_t gsrc, int tid) {
    int c  = tid & 15;
    int r0 = tid >> 4;
    #pragma unroll
    for (int i = 0; i < 8; ++i) {
        int r = r0 + 16 * i;
        uint32_t sw = (uint32_t)((((c ^ (r & 7)) & 7) | (c & 8)) << 4);
        cp_async16(sdst + r * 256 + sw, gsrc + (uint64_t)r * 256 + (uint64_t)c * 16);
    }
}

// one tile's 8 k-steps (k=32 each) into acc; when EPI, drain 2 cells of prev
// per k-step (16 cells total) with de-scale + exp.
template<bool EPI, bool DIAG>
__device__ __forceinline__ void tile_step(
    uint32_t bbuf, const uint32_t aRow[4], const uint32_t bRow[2],
    int lha, int lhb, int sa, int sbw,
    int acc[4][4][4], int prev[4][4][4],
    float rowsum[4][2], float cv0[4], float cv1[4],
    int rb, int cb, const float esd[8],
    const float rscE[4], const float rscO[4],
    const float csc0[4], const float csc1[4])
{
    #pragma unroll
    for (int ks = 0; ks < 8; ++ks) {
        int cA = 2 * ks + lha;
        int cB = 2 * ks + lhb;
        uint32_t offA = (uint32_t)((((cA ^ sa) & 7) | (cA & 8)) << 4);
        uint32_t offB = (uint32_t)((((cB ^ sbw) & 7) | (cB & 8)) << 4);

        uint32_t afr[4][4];
        #pragma unroll
        for (int mb = 0; mb < 4; ++mb) lm4(aRow[mb] + offA, afr[mb]);
        uint32_t bfr[2][4];
        #pragma unroll
        for (int n2 = 0; n2 < 2; ++n2) lm4(bbuf + bRow[n2] + offB, bfr[n2]);

        #pragma unroll
        for (int mb = 0; mb < 4; ++mb)
            #pragma unroll
            for (int nb = 0; nb < 4; ++nb)
                imma16832(acc[mb][nb], afr[mb],
                          bfr[nb >> 1][(nb & 1) * 2], bfr[nb >> 1][(nb & 1) * 2 + 1]);

        if (EPI) {
            #pragma unroll
            for (int e = 0; e < 2; ++e) {
                const int cell = 2 * ks + e;
                const int mb = cell >> 2, nb = cell & 3;
                float k00 = rscE[mb] * csc0[nb];
                float k01 = rscE[mb] * csc1[nb];
                float k10 = rscO[mb] * csc0[nb];
                float k11 = rscO[mb] * csc1[nb];
                float e0 = ex2f(fmaf((float)prev[mb][nb][0], k00, -EX2_SCALE));
                float e1 = ex2f(fmaf((float)prev[mb][nb][1], k01, -EX2_SCALE));
                float e2 = ex2f(fmaf((float)prev[mb][nb][2], k10, -EX2_SCALE));
                float e3 = ex2f(fmaf((float)prev[mb][nb][3], k11, -EX2_SCALE));
                if (DIAG) {
                    int rbm = rb + mb * 16;
                    int cbn = cb + nb * 8;
                    if (rbm == cbn)         e0 = esd[2 * mb];
                    if (rbm == cbn + 1)     e1 = esd[2 * mb];
                    if (rbm + 8 == cbn)     e2 = esd[2 * mb + 1];
                    if (rbm + 8 == cbn + 1) e3 = esd[2 * mb + 1];
                }
                rowsum[mb][0] += e0 + e1;
                rowsum[mb][1] += e2 + e3;
                cv0[nb] += e0 + e2;
                cv1[nb] += e1 + e3;
                prev[mb][nb][0] = 0; prev[mb][nb][1] = 0;
                prev[mb][nb][2] = 0; prev[mb][nb][3] = 0;
            }
        }
    }
}

template<bool DIAG>
__device__ __forceinline__ void drain_acc(int acc[4][4][4],
                                          float rowsum[4][2], float cv0[4], float cv1[4],
                                          int rb, int cb, const float esd[8],
                                          const float rscE[4], const float rscO[4],
                                          const float csc0[4], const float csc1[4]) {
    #pragma unroll
    for (int mb = 0; mb < 4; ++mb)
        #pragma unroll
        for (int nb = 0; nb < 4; ++nb) {
            float k00 = rscE[mb] * csc0[nb];
            float k01 = rscE[mb] * csc1[nb];
            float k10 = rscO[mb] * csc0[nb];
            float k11 = rscO[mb] * csc1[nb];
            float e0 = ex2f(fmaf((float)acc[mb][nb][0], k00, -EX2_SCALE));
            float e1 = ex2f(fmaf((float)acc[mb][nb][1], k01, -EX2_SCALE));
            float e2 = ex2f(fmaf((float)acc[mb][nb][2], k10, -EX2_SCALE));
            float e3 = ex2f(fmaf((float)acc[mb][nb][3], k11, -EX2_SCALE));
            if (DIAG) {
                int rbm = rb + mb * 16;
                int cbn = cb + nb * 8;
                if (rbm == cbn)         e0 = esd[2 * mb];
                if (rbm == cbn + 1)     e1 = esd[2 * mb];
                if (rbm + 8 == cbn)     e2 = esd[2 * mb + 1];
                if (rbm + 8 == cbn + 1) e3 = esd[2 * mb + 1];
            }
            rowsum[mb][0] += e0 + e1;
            rowsum[mb][1] += e2 + e3;
            cv0[nb] += e0 + e2;
            cv1[nb] += e1 + e3;
            acc[mb][nb][0] = 0; acc[mb][nb][1] = 0;
            acc[mb][nb][2] = 0; acc[mb][nb][3] = 0;
        }
}

__device__ __forceinline__ void flush_cols(float cv0[4], float cv1[4],
                                           int J, int wc, int l) {
    #pragma unroll
    for (int nb = 0; nb < 4; ++nb) {
        float v0 = cv0[nb], v1 = cv1[nb];
        v0 += __shfl_xor_sync(0xffffffffu, v0, 4);
        v1 += __shfl_xor_sync(0xffffffffu, v1, 4);
        v0 += __shfl_xor_sync(0xffffffffu, v0, 8);
        v1 += __shfl_xor_sync(0xffffffffu, v1, 8);
        v0 += __shfl_xor_sync(0xffffffffu, v0, 16);
        v1 += __shfl_xor_sync(0xffffffffu, v1, 16);
        if (l < 4) {
            int col = J * TILE + wc * 32 + nb * 8 + 2 * l;
            atomicAdd(&g_rowsum[col],     v0);
            atomicAdd(&g_rowsum[col + 1], v1);
        }
        cv0[nb] = 0.f; cv1[nb] = 0.f;
    }
}

__device__ __forceinline__ void zero_cv(float cv0[4], float cv1[4]) {
    cv0[0]=cv0[1]=cv0[2]=cv0[3]=0.f;
    cv1[0]=cv1[1]=cv1[2]=cv1[3]=0.f;
}

__device__ __forceinline__ void load_csc(float csc0[4], float csc1[4], int J, int cb) {
    #pragma unroll
    for (int nb = 0; nb < 4; ++nb) {
        int col = J * TILE + cb + nb * 8;
        csc0[nb] = g_scale[col];
        csc1[nb] = g_scale[col + 1];
    }
}

__global__ void __launch_bounds__(THREADS, 1) contrastive_main_kernel() {
    int bid = blockIdx.x;
    int tid = threadIdx.x;
    int l   = tid & 31;
    int wid = tid >> 5;
    int wr  = wid >> 2;
    int wc  = wid & 3;
    uint32_t sb = smem_u32(dyn_smem);

    uint64_t gbase;
    asm("cvta.to.global.u64 %0, %1;" : "=l"(gbase) : "l"((const void*)g_emb8));

    // lane maps (int8, 256B rows)
    int lha = l >> 4;          // A k-half
    int sa  = l & 7;           // A swizzle key (row&7)
    int lbB = (l & 7) + ((l >> 4) << 3);   // B col-row within 16
    int lhb = (l >> 3) & 1;    // B k-half
    int sbw = lbB & 7;

    int rb = wr * 64 + (l >> 2);
    int cb = wc * 32 + 2 * (l & 3);

    uint32_t aRow[4], bRow[2];
    #pragma unroll
    for (int mb = 0; mb < 4; ++mb)
        aRow[mb] = sb + SM_A + (uint32_t)(wr * 64 + mb * 16 + (l & 15)) * 256;
    #pragma unroll
    for (int n2 = 0; n2 < 2; ++n2)
        bRow[n2] = (uint32_t)(wc * 32 + n2 * 16 + lbB) * 256;

    int accE[4][4][4], accO[4][4][4];
    #pragma unroll
    for (int mb = 0; mb < 4; ++mb)
        #pragma unroll
        for (int nb = 0; nb < 4; ++nb)
            #pragma unroll
            for (int k = 0; k < 4; ++k) { accE[mb][nb][k] = 0; accO[mb][nb][k] = 0; }

    float cv0[4] = {0,0,0,0}, cv1[4] = {0,0,0,0};
    float esd[8] = {0,0,0,0,0,0,0,0};
    float rscE[4], rscO[4], csc0[4], csc1[4];

    // persistent scheduler: linearized triangle, paired row order
    int start = (int)(((long long)bid       * TOTAL_TILES) / GRID);
    int end   = (int)(((long long)(bid + 1) * TOTAL_TILES) / GRID);

    int s = 0, I = 0, cum = 0;
    for (;; ++s) {
        I = (s & 1) ? (NT - 1 - (s >> 1)) : (s >> 1);
        int rowlen = NT - I;
        if (cum + rowlen > start) break;
        cum += rowlen;
    }
    int J0  = I + (start - cum);
    int idx = start;

    while (idx < end) {
        int cnt = min(end - idx, NT - J0);
        bool runDiag = (J0 == I);

        stage_tile(sb + SM_A,  gbase + (uint64_t)I * TILE * 256, tid);
        stage_tile(sb + SM_B0, gbase + (uint64_t)J0 * TILE * 256, tid);
        cp_commit();
        if (cnt > 1) {
            stage_tile(sb + SM_B1, gbase + (uint64_t)(J0 + 1) * TILE * 256, tid);
            cp_commit();
        }

        // per-run row factors and (if diag) exact diagonal exps
        #pragma unroll
        for (int mb = 0; mb < 4; ++mb) {
            rscE[mb] = EX2_SCALE * g_scale[I * TILE + rb + mb * 16];
            rscO[mb] = EX2_SCALE * g_scale[I * TILE + rb + mb * 16 + 8];
        }
        if (runDiag) {
            #pragma unroll
            for (int mb = 0; mb < 4; ++mb) {
                float sd0 = g_selfdot[I * TILE + rb + mb * 16];
                float sd1 = g_selfdot[I * TILE + rb + mb * 16 + 8];
                esd[2 * mb]     = ex2f(fmaf(sd0, EX2_SCALE, -EX2_SCALE));
                esd[2 * mb + 1] = ex2f(fmaf(sd1, EX2_SCALE, -EX2_SCALE));
            }
        }

        float rowsum[4][2];
        #pragma unroll
        for (int mb = 0; mb < 4; ++mb) { rowsum[mb][0] = 0.f; rowsum[mb][1] = 0.f; }

        int Jprev = -1;

        for (int t = 0; t < cnt; ++t) {
            if (t == cnt - 1) asm volatile("cp.async.wait_group 0;" ::: "memory");
            else              asm volatile("cp.async.wait_group 1;" ::: "memory");
            __syncthreads();

            uint32_t bbuf = sb + ((t & 1) ? SM_B1 : SM_B0);

            if (t > 0) load_csc(csc0, csc1, Jprev, cb);   // scales for prev tile's cols

            if (t == 0)
                tile_step<false,false>(bbuf, aRow, bRow, lha, lhb, sa, sbw,
                                       accE, accO, rowsum, cv0, cv1, rb, cb, esd,
                                       rscE, rscO, csc0, csc1);
            else if (t == 1 && runDiag)
                tile_step<true,true>(bbuf, aRow, bRow, lha, lhb, sa, sbw,
                                     accO, accE, rowsum, cv0, cv1, rb, cb, esd,
                                     rscE, rscO, csc0, csc1);
            else if (t & 1)
                tile_step<true,false>(bbuf, aRow, bRow, lha, lhb, sa, sbw,
                                      accO, accE, rowsum, cv0, cv1, rb, cb, esd,
                                      rscE, rscO, csc0, csc1);
            else
                tile_step<true,false>(bbuf, aRow, bRow, lha, lhb, sa, sbw,
                                      accE, accO, rowsum, cv0, cv1, rb, cb, esd,
                                      rscE, rscO, csc0, csc1);
            __syncthreads();

            if (t + 2 < cnt) {
                stage_tile(sb + ((t & 1) ? SM_B1 : SM_B0),
                           gbase + (uint64_t)(J0 + t + 2) * TILE * 256, tid);
                cp_commit();
            }

            if (t > 0) {
                if (Jprev != I) flush_cols(cv0, cv1, Jprev, wc, l);
                else            zero_cv(cv0, cv1);
            }
            Jprev = J0 + t;
        }

        // drain the run's final tile
        load_csc(csc0, csc1, Jprev, cb);
        {
            int (*lastAcc)[4][4] = ((cnt - 1) & 1) ? accO : accE;
            if (cnt == 1 && runDiag)
                drain_acc<true>(lastAcc, rowsum, cv0, cv1, rb, cb, esd,
                                rscE, rscO, csc0, csc1);
            else
                drain_acc<false>(lastAcc, rowsum, cv0, cv1, rb, cb, esd,
                                 rscE, rscO, csc0, csc1);
        }
        if (Jprev != I) flush_cols(cv0, cv1, Jprev, wc, l);
        else            zero_cv(cv0, cv1);

        // flush row sums for this run's I block
        #pragma unroll
        for (int mb = 0; mb < 4; ++mb) {
            #pragma unroll
            for (int ss = 0; ss < 2; ++ss) {
                float p = rowsum[mb][ss];
                p += __shfl_xor_sync(0xffffffffu, p, 1);
                p += __shfl_xor_sync(0xffffffffu, p, 2);
                if ((l & 3) == 0) {
                    int row = I * TILE + wr * 64 + mb * 16 + ss * 8 + (l >> 2);
                    atomicAdd(&g_rowsum[row], p);
                }
            }
        }

        idx += cnt;
        ++s;
        I  = (s & 1) ? (NT - 1 - (s >> 1)) : (s >> 1);
        J0 = I;
    }
}

// ---------------------------------------------------------------------------
// Kernel 3: loss_i = log(rowsum_i) + (1 - selfdot_i)/T;  out = mean
// ---------------------------------------------------------------------------
__global__ void __launch_bounds__(1024) finalize_kernel(float* __restrict__ out) {
    int t = threadIdx.x;
    float acc = 0.f;
    #pragma unroll
    for (int i = 0; i < 16; ++i) {
        int r = t + i * 1024;
        acc += logf(g_rowsum[r]) + (1.0f - g_selfdot[r]) * INV_T;
    }
    #pragma unroll
    for (int o = 16; o; o >>= 1) acc += __shfl_xor_sync(0xffffffffu, acc, o);
    __shared__ float red[32];
    if ((t & 31) == 0) red[t >> 5] = acc;
    __syncthreads();
    if (t < 32) {
        float v = red[t];
        #pragma unroll
        for (int o = 16; o; o >>= 1) v += __shfl_xor_sync(0xffffffffu, v, o);
        if (t == 0) out[0] = v * (1.0f / (float)N_ROWS);
    }
}

// ---------------------------------------------------------------------------
extern "C" void kernel_launch(void* const* d_in, const int* in_sizes, int n_in,
                              void* d_out, int out_size) {
    const float* emb = (const float*)d_in[0];
    float* out = (float*)d_out;
    (void)in_sizes; (void)n_in; (void)out_size;

    cudaFuncSetAttribute(contrastive_main_kernel,
                         cudaFuncAttributeMaxDynamicSharedMemorySize, SM_TOTAL);

    normalize_kernel<<<N_ROWS / 8, 256>>>(emb);
    contrastive_main_kernel<<<GRID, THREADS, SM_TOTAL>>>();
    finalize_kernel<<<1, 1024>>>(out);
}

// round 11
// speedup vs baseline: 2.3183x; 2.3183x over previous
#include <cuda_runtime.h>
#include <cuda_bf16.h>
#include <cstdint>

// ============================================================================
// ContrastiveLoss: N=16384, D=256, T=0.07
// loss = mean_i [ log(sum_j exp((c_ij - 1)/T)) + (1 - selfdot_i)/T ]
// R11: single fused persistent kernel (normalize -> grid sync -> triangle
// GEMM+exp (bf16 HMMA, fp32 accum, interleaved MUFU epilogue) -> last-CTA
// finalize). Phase 2 is the measured-fastest R5 path (at the fallback-tensor
// issue roofline ~12.5 cyc/HMMA/SMSP).
// ============================================================================

#define N_ROWS 16384
#define DIM    256
#define TILE   128
#define NT     (N_ROWS / TILE)   // 128
#define THREADS 256
#define GRID   148
#define NWARPS_G (GRID * 8)      // 1184 global warps
#define TOTAL_TILES (NT * (NT + 1) / 2)   // 8256

#define INV_T      14.285714285714286f
#define EX2_SCALE  20.60992915555662f   // log2(e)/0.07

__device__ __nv_bfloat16 g_embn[N_ROWS * DIM];   // normalized bf16 rows (512B/row)
__device__ float g_selfdot[N_ROWS];
__device__ float g_rowsum[N_ROWS];
__device__ int   g_c1;   // phase-1 barrier counter (reset at kernel end)
__device__ int   g_c2;   // phase-2 arrival counter (reset at kernel end)

// ---------------------------------------------------------------------------
__device__ __forceinline__ uint32_t smem_u32(const void* p) {
    uint32_t a;
    asm("{ .reg .u64 t; cvta.to.shared.u64 t, %1; cvt.u32.u64 %0, t; }" : "=r"(a) : "l"(p));
    return a;
}

__device__ __forceinline__ float ex2f(float x) {
    float y;
    asm("ex2.approx.ftz.f32 %0, %1;" : "=f"(y) : "f"(x));
    return y;
}

#define SWZ16(row, c16) (((((c16) ^ (row)) & 7) | ((c16) & 24)))

__device__ __forceinline__ void lm4(uint32_t addr, uint32_t r[4]) {
    asm volatile("ldmatrix.sync.aligned.m8n8.x4.shared.b16 {%0,%1,%2,%3}, [%4];"
                 : "=r"(r[0]), "=r"(r[1]), "=r"(r[2]), "=r"(r[3]) : "r"(addr));
}

__device__ __forceinline__ void mma16816(float c[4], const uint32_t a[4],
                                         uint32_t b0, uint32_t b1) {
    asm volatile(
        "mma.sync.aligned.m16n8k16.row.col.f32.bf16.bf16.f32 "
        "{%0,%1,%2,%3}, {%4,%5,%6,%7}, {%8,%9}, {%0,%1,%2,%3};"
        : "+f"(c[0]), "+f"(c[1]), "+f"(c[2]), "+f"(c[3])
        : "r"(a[0]), "r"(a[1]), "r"(a[2]), "r"(a[3]), "r"(b0), "r"(b1));
}

__device__ __forceinline__ void cp_async16(uint32_t dst, uint64_t src) {
    asm volatile("cp.async.cg.shared.global [%0], [%1], 16;" :: "r"(dst), "l"(src) : "memory");
}
__device__ __forceinline__ void cp_commit() {
    asm volatile("cp.async.commit_group;" ::: "memory");
}

// ---------------------------------------------------------------------------
// smem layout: A 64KB + B double buffer 128KB
// ---------------------------------------------------------------------------
#define SM_A     0
#define SM_B0    65536
#define SM_B1    131072
#define SM_TOTAL 196608

extern __shared__ char dyn_smem[];

__device__ __forceinline__ void stage_tile(uint32_t sdst, uint64_t gsrc, int tid) {
    int c  = tid & 31;
    int r0 = tid >> 5;
    #pragma unroll
    for (int i = 0; i < 16; ++i) {
        int r = r0 + 8 * i;
        uint32_t d = sdst + r * 512 + SWZ16(r, c) * 16;
        cp_async16(d, gsrc + (uint64_t)r * 512 + (uint64_t)c * 16);
    }
}

// one tile's 16 k-steps; optionally interleave exp-epilogue of prev tile
template<bool EPI>
__device__ __forceinline__ void tile_step(
    uint32_t bbuf, const uint32_t aRow[4], const uint32_t bRow[2],
    int lha, int lhb, int sa, int sbw,
    float acc[4][4][4], float prev[4][4][4],
    float rowsum[4][2], float cv0[4], float cv1[4])
{
    #pragma unroll
    for (int ks = 0; ks < 16; ++ks) {
        int cA = 2 * ks + lha;
        int cB = 2 * ks + lhb;
        uint32_t offA = (uint32_t)((((cA ^ sa) & 7) | (cA & 24)) << 4);
        uint32_t offB = (uint32_t)((((cB ^ sbw) & 7) | (cB & 24)) << 4);

        uint32_t afr[4][4];
        #pragma unroll
        for (int mb = 0; mb < 4; ++mb) lm4(aRow[mb] + offA, afr[mb]);
        uint32_t bfr[2][4];
        #pragma unroll
        for (int n2 = 0; n2 < 2; ++n2) lm4(bbuf + bRow[n2] + offB, bfr[n2]);

        #pragma unroll
        for (int mb = 0; mb < 4; ++mb)
            #pragma unroll
            for (int nb = 0; nb < 4; ++nb)
                mma16816(acc[mb][nb], afr[mb],
                         bfr[nb >> 1][(nb & 1) * 2], bfr[nb >> 1][(nb & 1) * 2 + 1]);

        if (EPI) {
            const int mb = ks >> 2, nb = ks & 3;
            float e0 = ex2f(fmaf(prev[mb][nb][0], EX2_SCALE, -EX2_SCALE));
            float e1 = ex2f(fmaf(prev[mb][nb][1], EX2_SCALE, -EX2_SCALE));
            float e2 = ex2f(fmaf(prev[mb][nb][2], EX2_SCALE, -EX2_SCALE));
            float e3 = ex2f(fmaf(prev[mb][nb][3], EX2_SCALE, -EX2_SCALE));
            rowsum[mb][0] += e0 + e1;
            rowsum[mb][1] += e2 + e3;
            cv0[nb] += e0 + e2;
            cv1[nb] += e1 + e3;
        }
    }
}

__device__ __forceinline__ void flush_cols(float cv0[4], float cv1[4],
                                           int J, int wc, int l) {
    #pragma unroll
    for (int nb = 0; nb < 4; ++nb) {
        float v0 = cv0[nb], v1 = cv1[nb];
        v0 += __shfl_xor_sync(0xffffffffu, v0, 4);
        v1 += __shfl_xor_sync(0xffffffffu, v1, 4);
        v0 += __shfl_xor_sync(0xffffffffu, v0, 8);
        v1 += __shfl_xor_sync(0xffffffffu, v1, 8);
        v0 += __shfl_xor_sync(0xffffffffu, v0, 16);
        v1 += __shfl_xor_sync(0xffffffffu, v1, 16);
        if (l < 4) {
            int col = J * TILE + wc * 32 + nb * 8 + 2 * l;
            atomicAdd(&g_rowsum[col],     v0);
            atomicAdd(&g_rowsum[col + 1], v1);
        }
        cv0[nb] = 0.f; cv1[nb] = 0.f;
    }
}

__device__ __forceinline__ void zero_cv(float cv0[4], float cv1[4]) {
    cv0[0]=cv0[1]=cv0[2]=cv0[3]=0.f;
    cv1[0]=cv1[1]=cv1[2]=cv1[3]=0.f;
}

// ---------------------------------------------------------------------------
// The fused persistent kernel
// ---------------------------------------------------------------------------
__global__ void __launch_bounds__(THREADS, 1)
contrastive_fused_kernel(const float* __restrict__ in, float* __restrict__ out) {
    int bid = blockIdx.x;
    int tid = threadIdx.x;
    int l   = tid & 31;
    int wid = tid >> 5;

    // ===================== Phase 1: normalize -> bf16 =====================
    {
        int gwarp = bid * 8 + wid;
        for (int it = 0; it < 14; ++it) {
            int row = gwarp + NWARPS_G * it;
            if (row < N_ROWS) {
                const float4* p = reinterpret_cast<const float4*>(in + (size_t)row * DIM);
                float4 a = p[l];
                float4 b = p[l + 32];

                float s = a.x*a.x + a.y*a.y + a.z*a.z + a.w*a.w
                        + b.x*b.x + b.y*b.y + b.z*b.z + b.w*b.w;
                #pragma unroll
                for (int o = 16; o; o >>= 1) s += __shfl_xor_sync(0xffffffffu, s, o);

                float inv = 1.0f / sqrtf(s);

                __nv_bfloat16 q[8];
                q[0] = __float2bfloat16(a.x * inv); q[1] = __float2bfloat16(a.y * inv);
                q[2] = __float2bfloat16(a.z * inv); q[3] = __float2bfloat16(a.w * inv);
                q[4] = __float2bfloat16(b.x * inv); q[5] = __float2bfloat16(b.y * inv);
                q[6] = __float2bfloat16(b.z * inv); q[7] = __float2bfloat16(b.w * inv);

                float sd = 0.f;
                #pragma unroll
                for (int k = 0; k < 8; ++k) { float f = __bfloat162float(q[k]); sd += f * f; }
                #pragma unroll
                for (int o = 16; o; o >>= 1) sd += __shfl_xor_sync(0xffffffffu, sd, o);

                uint2* qo = reinterpret_cast<uint2*>(g_embn + (size_t)row * DIM);
                __nv_bfloat162 h01, h23, h45, h67;
                h01.x = q[0]; h01.y = q[1]; h23.x = q[2]; h23.y = q[3];
                h45.x = q[4]; h45.y = q[5]; h67.x = q[6]; h67.y = q[7];
                uint2 u0, u1;
                u0.x = *reinterpret_cast<uint32_t*>(&h01);
                u0.y = *reinterpret_cast<uint32_t*>(&h23);
                u1.x = *reinterpret_cast<uint32_t*>(&h45);
                u1.y = *reinterpret_cast<uint32_t*>(&h67);
                qo[l]      = u0;
                qo[l + 32] = u1;

                if (l == 0) g_selfdot[row] = sd;
                if (l == 1) g_rowsum[row] = 0.f;
            }
        }
    }

    // ===================== grid barrier =====================
    __syncthreads();
    if (tid == 0) {
        __threadfence();
        atomicAdd(&g_c1, 1);
        while (*(volatile int*)&g_c1 < GRID) { }
        __threadfence();
    }
    __syncthreads();

    // ===================== Phase 2: triangle GEMM + exp =====================
    {
        int wr = wid >> 2;
        int wc = wid & 3;
        uint32_t sb = smem_u32(dyn_smem);

        uint64_t gbase;
        asm("cvta.to.global.u64 %0, %1;" : "=l"(gbase) : "l"((const void*)g_embn));

        int la  = l & 15;
        int lha = l >> 4;
        int sa  = la & 7;
        int lb  = (l & 7) + ((l >> 4) << 3);
        int lhb = (l >> 3) & 1;
        int sbw = lb & 7;

        uint32_t aRow[4], bRow[2];
        #pragma unroll
        for (int mb = 0; mb < 4; ++mb)
            aRow[mb] = sb + SM_A + (uint32_t)(wr * 64 + mb * 16 + la) * 512;
        #pragma unroll
        for (int n2 = 0; n2 < 2; ++n2)
            bRow[n2] = (uint32_t)(wc * 32 + n2 * 16 + lb) * 512;

        float acc[4][4][4], prev[4][4][4];
        #pragma unroll
        for (int mb = 0; mb < 4; ++mb)
            #pragma unroll
            for (int nb = 0; nb < 4; ++nb)
                #pragma unroll
                for (int k = 0; k < 4; ++k) { acc[mb][nb][k] = 0.f; prev[mb][nb][k] = 0.f; }

        float cv0[4] = {0,0,0,0}, cv1[4] = {0,0,0,0};

        // persistent scheduler: linearized triangle, paired row order
        int start = (int)(((long long)bid       * TOTAL_TILES) / GRID);
        int end   = (int)(((long long)(bid + 1) * TOTAL_TILES) / GRID);

        int s = 0, I = 0, cum = 0;
        for (;; ++s) {
            I = (s & 1) ? (NT - 1 - (s >> 1)) : (s >> 1);
            int rowlen = NT - I;
            if (cum + rowlen > start) break;
            cum += rowlen;
        }
        int J0  = I + (start - cum);
        int idx = start;

        while (idx < end) {
            int cnt = min(end - idx, NT - J0);

            stage_tile(sb + SM_A,  gbase + (uint64_t)I * TILE * 512, tid);
            stage_tile(sb + SM_B0, gbase + (uint64_t)J0 * TILE * 512, tid);
            cp_commit();
            if (cnt > 1) {
                stage_tile(sb + SM_B1, gbase + (uint64_t)(J0 + 1) * TILE * 512, tid);
                cp_commit();
            }

            float rowsum[4][2];
            #pragma unroll
            for (int mb = 0; mb < 4; ++mb) { rowsum[mb][0] = 0.f; rowsum[mb][1] = 0.f; }

            int Jprev = -1;

            for (int t = 0; t < cnt; ++t) {
                if (t == cnt - 1) asm volatile("cp.async.wait_group 0;" ::: "memory");
                else              asm volatile("cp.async.wait_group 1;" ::: "memory");
                __syncthreads();

                uint32_t bbuf = sb + ((t & 1) ? SM_B1 : SM_B0);

                if (t == 0)
                    tile_step<false>(bbuf, aRow, bRow, lha, lhb, sa, sbw,
                                     acc, prev, rowsum, cv0, cv1);
                else
                    tile_step<true>(bbuf, aRow, bRow, lha, lhb, sa, sbw,
                                    acc, prev, rowsum, cv0, cv1);
                __syncthreads();

                if (t + 2 < cnt) {
                    stage_tile(sb + ((t & 1) ? SM_B1 : SM_B0),
                               gbase + (uint64_t)(J0 + t + 2) * TILE * 512, tid);
                    cp_commit();
                }

                if (t > 0) {
                    if (Jprev != I) flush_cols(cv0, cv1, Jprev, wc, l);
                    else            zero_cv(cv0, cv1);
                }

                // rotate acc -> prev, zero acc
                #pragma unroll
                for (int mb = 0; mb < 4; ++mb)
                    #pragma unroll
                    for (int nb = 0; nb < 4; ++nb)
                        #pragma unroll
                        for (int k = 0; k < 4; ++k) {
                            prev[mb][nb][k] = acc[mb][nb][k];
                            acc[mb][nb][k]  = 0.f;
                        }
                Jprev = J0 + t;
            }

            // drain the run's final tile
            #pragma unroll
            for (int mb = 0; mb < 4; ++mb)
                #pragma unroll
                for (int nb = 0; nb < 4; ++nb) {
                    float e0 = ex2f(fmaf(prev[mb][nb][0], EX2_SCALE, -EX2_SCALE));
                    float e1 = ex2f(fmaf(prev[mb][nb][1], EX2_SCALE, -EX2_SCALE));
                    float e2 = ex2f(fmaf(prev[mb][nb][2], EX2_SCALE, -EX2_SCALE));
                    float e3 = ex2f(fmaf(prev[mb][nb][3], EX2_SCALE, -EX2_SCALE));
                    rowsum[mb][0] += e0 + e1;
                    rowsum[mb][1] += e2 + e3;
                    cv0[nb] += e0 + e2;
                    cv1[nb] += e1 + e3;
                    prev[mb][nb][0] = 0.f; prev[mb][nb][1] = 0.f;
                    prev[mb][nb][2] = 0.f; prev[mb][nb][3] = 0.f;
                }
            if (Jprev != I) flush_cols(cv0, cv1, Jprev, wc, l);
            else            zero_cv(cv0, cv1);

            // flush row sums for this run's I block
            #pragma unroll
            for (int mb = 0; mb < 4; ++mb) {
                #pragma unroll
                for (int ss = 0; ss < 2; ++ss) {
                    float p = rowsum[mb][ss];
                    p += __shfl_xor_sync(0xffffffffu, p, 1);
                    p += __shfl_xor_sync(0xffffffffu, p, 2);
                    if ((l & 3) == 0) {
                        int row = I * TILE + wr * 64 + mb * 16 + ss * 8 + (l >> 2);
                        atomicAdd(&g_rowsum[row], p);
                    }
                }
            }

            idx += cnt;
            ++s;
            I  = (s & 1) ? (NT - 1 - (s >> 1)) : (s >> 1);
            J0 = I;
        }
    }

    // ===================== Phase 3: last CTA finalizes =====================
    __shared__ int sIsLast;
    __syncthreads();
    if (tid == 0) {
        __threadfence();
        int old = atomicAdd(&g_c2, 1);
        sIsLast = (old == GRID - 1) ? 1 : 0;
    }
    __syncthreads();

    if (sIsLast) {
        __threadfence();   // acquire remote g_rowsum atomics
        float acc = 0.f;
        #pragma unroll
        for (int i = 0; i < 64; ++i) {
            int r = tid + i * THREADS;
            acc += logf(g_rowsum[r]) + (1.0f - g_selfdot[r]) * INV_T;
        }
        #pragma unroll
        for (int o = 16; o; o >>= 1) acc += __shfl_xor_sync(0xffffffffu, acc, o);
        float* red = reinterpret_cast<float*>(dyn_smem);   // phase-2 smem reusable now
        if (l == 0) red[wid] = acc;
        __syncthreads();
        if (tid == 0) {
            float v = 0.f;
            #pragma unroll
            for (int w = 0; w < 8; ++w) v += red[w];
            out[0] = v * (1.0f / (float)N_ROWS);
            g_c1 = 0;              // reset barriers for next graph replay
            g_c2 = 0;
            __threadfence();
        }
    }
}

// ---------------------------------------------------------------------------
extern "C" void kernel_launch(void* const* d_in, const int* in_sizes, int n_in,
                              void* d_out, int out_size) {
    const float* emb = (const float*)d_in[0];
    float* out = (float*)d_out;
    (void)in_sizes; (void)n_in; (void)out_size;

    cudaFuncSetAttribute(contrastive_fused_kernel,
                         cudaFuncAttributeMaxDynamicSharedMemorySize, SM_TOTAL);

    contrastive_fused_kernel<<<GRID, THREADS, SM_TOTAL>>>(emb, out);
}